// round 6
// baseline (speedup 1.0000x reference)
#include <cuda_runtime.h>

#define BB 256
#define LL 500
#define EE 300
#define NROWS (BB * LL)          // 128000
#define NWV 18                   // 3 + 5 + 7 conv rows + 3 cw rows

// ---- dots kernel config ----
#define T1 128                   // 4 warps -> all 4 SMSPs used
#define TROWS 128                // rows per block, 1 row per thread
#define EK 20                    // e-chunk (300 = 15 * 20)
#define NCHUNK 15
#define XSTR 32                  // words per x-row in smem (16 x 8B slots, swizzle space)
#define WSTR 20                  // words per w-row in smem

// 9.2 MB scratch for the 18 dot products per row
__device__ float g_Q[(size_t)NROWS * NWV];

__device__ __forceinline__ unsigned long long ffma2(unsigned long long a,
                                                    unsigned long long b,
                                                    unsigned long long c) {
    unsigned long long d;
    asm("fma.rn.f32x2 %0, %1, %2, %3;" : "=l"(d) : "l"(a), "l"(b), "l"(c));
    return d;
}

// ---------------------------------------------------------------------------
// Kernel 1: Q[row][0:18] = x[row] . W[wv]   (tall-skinny GEMM, f32x2 FMAs)
//   wv 0-2 : aw3 rows, 3-7 : aw5 rows, 8-14 : aw7 rows, 15/16/17 : cw3/5/7
// Each thread owns one x-row and all 18 accumulators; w loads are warp-broadcast.
// ---------------------------------------------------------------------------
__global__ __launch_bounds__(T1) void dots_kernel(
    const float* __restrict__ x,
    const float* __restrict__ aw3, const float* __restrict__ aw5,
    const float* __restrict__ aw7,
    const float* __restrict__ cw3, const float* __restrict__ cw5,
    const float* __restrict__ cw7)
{
    __shared__ __align__(16) float xs[TROWS * XSTR];   // 16 KB, swizzled
    __shared__ __align__(16) float ws[NWV * WSTR];     // 1.44 KB

    const int tid = threadIdx.x;
    const int r4  = tid & 15;
    const size_t rowBase = (size_t)blockIdx.x * TROWS;

    unsigned long long acc[NWV];
    #pragma unroll
    for (int c = 0; c < NWV; c++) acc[c] = 0ull;

    const float* xbase = x + rowBase * EE;

    #pragma unroll 1
    for (int ck = 0; ck < NCHUNK; ck++) {
        const int ce = ck * EK;

        // ---- stage x chunk: 128 rows x 20 floats (5 float4/row), swizzled
        #pragma unroll
        for (int it = 0; it < (TROWS * 5) / T1; it++) {
            int t = tid + it * T1;
            int row = t / 5, q = t % 5;
            float4 v = *reinterpret_cast<const float4*>(
                xbase + (size_t)row * EE + ce + q * 4);
            int rr = row & 15;
            float2* b2 = reinterpret_cast<float2*>(&xs[row * XSTR]);
            b2[(2 * q) ^ rr]     = make_float2(v.x, v.y);
            b2[(2 * q + 1) ^ rr] = make_float2(v.z, v.w);
        }

        // ---- stage w chunk: 18 rows x 20 floats (5 float4/row) = 90 loads
        if (tid < NWV * 5) {
            int wr = tid / 5, q = tid % 5;
            const float* src;
            if (wr < 3)       src = aw3 + wr * EE;
            else if (wr < 8)  src = aw5 + (wr - 3) * EE;
            else if (wr < 15) src = aw7 + (wr - 8) * EE;
            else              src = (wr == 15) ? cw3 : (wr == 16) ? cw5 : cw7;
            *reinterpret_cast<float4*>(&ws[wr * WSTR + q * 4]) =
                *reinterpret_cast<const float4*>(src + ce + q * 4);
        }
        __syncthreads();

        // ---- compute: per 4-e step: 2 LDS.64 (x) + 18 LDS.128 (w bcast) + 36 FFMA2
        #pragma unroll
        for (int e = 0; e < EK; e += 4) {
            const unsigned long long* xr =
                reinterpret_cast<const unsigned long long*>(&xs[tid * XSTR]);
            unsigned long long xa = xr[(e / 2) ^ r4];
            unsigned long long xb = xr[(e / 2 + 1) ^ r4];
            #pragma unroll
            for (int c = 0; c < NWV; c++) {
                ulonglong2 w2 = *reinterpret_cast<const ulonglong2*>(
                    &ws[c * WSTR + e]);            // broadcast LDS.128
                acc[c] = ffma2(xa, w2.x, acc[c]);
                acc[c] = ffma2(xb, w2.y, acc[c]);
            }
        }
        __syncthreads();
    }

    // ---- reduce pairs, stage in smem (reuse xs), write coalesced float4
    #pragma unroll
    for (int c = 0; c < NWV; c++) {
        float lo, hi;
        asm("mov.b64 {%0,%1}, %2;" : "=f"(lo), "=f"(hi) : "l"(acc[c]));
        xs[tid * NWV + c] = lo + hi;
    }
    __syncthreads();

    float* qdst = g_Q + rowBase * NWV;   // block's 128*18 region is contiguous
    #pragma unroll
    for (int t = tid; t < TROWS * NWV / 4; t += T1) {
        *reinterpret_cast<float4*>(qdst + t * 4) =
            *reinterpret_cast<const float4*>(&xs[t * 4]);
    }
}

// ---------------------------------------------------------------------------
// Kernel 2: shift-combine + activations, smem-tiled.
// Block = (b, 125-wide l tile). Loads Q rows [l0-3, l0+127] (halo zeroed ->
// implements conv zero-padding), then pure smem reads.
// ---------------------------------------------------------------------------
#define CT 125                   // l values per block
#define CROWS (CT + 6)           // 131 smem rows

__global__ __launch_bounds__(128) void combine_kernel(
    const float* __restrict__ ab3, const float* __restrict__ cb3,
    const float* __restrict__ ab5, const float* __restrict__ cb5,
    const float* __restrict__ ab7, const float* __restrict__ cb7,
    float* __restrict__ out)
{
    __shared__ float qs[CROWS * NWV];    // 9.4 KB

    const int tid  = threadIdx.x;
    const int b    = blockIdx.x >> 2;
    const int l0   = (blockIdx.x & 3) * CT;

    // load 131 rows x 9 float2 (coalesced; rows are contiguous in g_Q)
    for (int idx = tid; idx < CROWS * (NWV / 2); idx += 128) {
        int r = idx / (NWV / 2), p = idx % (NWV / 2);
        int lr = l0 - 3 + r;
        float2 v = make_float2(0.f, 0.f);
        if (lr >= 0 && lr < LL) {
            v = *reinterpret_cast<const float2*>(
                g_Q + ((size_t)b * LL + lr) * NWV + p * 2);
        }
        reinterpret_cast<float2*>(qs)[idx] = v;
    }
    __syncthreads();

    if (tid < CT) {
        const int c = tid + 3;           // smem row for l = l0 + tid
        float s3 = 0.f, s5 = 0.f, s7 = 0.f;
        #pragma unroll
        for (int j = 0; j < 3; j++) s3 += qs[(c + j - 1) * NWV + j];
        #pragma unroll
        for (int j = 0; j < 5; j++) s5 += qs[(c + j - 2) * NWV + 3 + j];
        #pragma unroll
        for (int j = 0; j < 7; j++) s7 += qs[(c + j - 3) * NWV + 8 + j];

        float d3 = qs[c * NWV + 15];
        float d5 = qs[c * NWV + 16];
        float d7 = qs[c * NWV + 17];

        float sc3 = 1.f / (1.f + __expf(-(s3 + ab3[0])));
        float sc5 = 1.f / (1.f + __expf(-(s5 + ab5[0])));
        float sc7 = 1.f / (1.f + __expf(-(s7 + ab7[0])));

        int row = b * LL + l0 + tid;
        out[row]             = tanhf(sc3 * d3 + cb3[0]);
        out[NROWS + row]     = tanhf(sc5 * d5 + cb5[0]);
        out[2 * NROWS + row] = tanhf(sc7 * d7 + cb7[0]);
    }
}

// ---------------------------------------------------------------------------
extern "C" void kernel_launch(void* const* d_in, const int* in_sizes, int n_in,
                              void* d_out, int out_size) {
    const float* x   = (const float*)d_in[0];
    const float* aw3 = (const float*)d_in[1];
    const float* ab3 = (const float*)d_in[2];
    const float* cw3 = (const float*)d_in[3];
    const float* cb3 = (const float*)d_in[4];
    const float* aw5 = (const float*)d_in[5];
    const float* ab5 = (const float*)d_in[6];
    const float* cw5 = (const float*)d_in[7];
    const float* cb5 = (const float*)d_in[8];
    const float* aw7 = (const float*)d_in[9];
    const float* ab7 = (const float*)d_in[10];
    const float* cw7 = (const float*)d_in[11];
    const float* cb7 = (const float*)d_in[12];
    float* out = (float*)d_out;

    dots_kernel<<<NROWS / TROWS, T1>>>(x, aw3, aw5, aw7, cw3, cw5, cw7);
    combine_kernel<<<BB * 4, 128>>>(ab3, cb3, ab5, cb5, ab7, cb7, out);
}

// round 8
// speedup vs baseline: 1.8301x; 1.8301x over previous
#include <cuda_runtime.h>

#define BB 256
#define LL 500
#define EE 300
#define NROWS (BB * LL)          // 128000
#define NWV 18                   // 3 + 5 + 7 conv rows + 3 cw rows

// ---- dots kernel config ----
#define T1 128                   // 4 warps -> all 4 SMSPs
#define TROWS 128                // rows per block (each thread: 2 rows x 9 wv)
#define EK 60                    // e-chunk (300 = 5 * 60)
#define NCHUNK 5
#define XSTR 64                  // words per x-row in smem (32 x 8B slots, swizzled)
#define WSTR 60                  // words per w-row in smem

// 9.2 MB scratch for the 18 dot products per row
__device__ float g_Q[(size_t)NROWS * NWV];

__device__ __forceinline__ unsigned long long ffma2(unsigned long long a,
                                                    unsigned long long b,
                                                    unsigned long long c) {
    unsigned long long d;
    asm("fma.rn.f32x2 %0, %1, %2, %3;" : "=l"(d) : "l"(a), "l"(b), "l"(c));
    return d;
}

// ---------------------------------------------------------------------------
// Kernel 1: Q[row][0:18] = x[row] . W[wv]   (tall-skinny GEMM, f32x2 FMAs)
//   wv 0-2 : aw3 rows, 3-7 : aw5 rows, 8-14 : aw7 rows, 15/16/17 : cw3/5/7
// Warp w: cgrp = w&1 (wv 0-8 / 9-17), rgrp = w>>1. Thread handles rows
// r0 = rgrp*32+lane and r0+64. Per 4-e step/warp: 9 LDS.128 + 4 LDS.64 +
// 36 FFMA2  ->  17 crossbar wavefronts vs 72 FMA cyc  ->  FMA-bound.
// ---------------------------------------------------------------------------
__global__ __launch_bounds__(T1) void dots_kernel(
    const float* __restrict__ x,
    const float* __restrict__ aw3, const float* __restrict__ aw5,
    const float* __restrict__ aw7,
    const float* __restrict__ cw3, const float* __restrict__ cw5,
    const float* __restrict__ cw7)
{
    __shared__ __align__(16) float xs[TROWS * XSTR];   // 32 KB, swizzled
    __shared__ __align__(16) float ws[NWV * WSTR];     // 4.3 KB

    const int tid  = threadIdx.x;
    const int lane = tid & 31;
    const int w    = tid >> 5;
    const int cgrp = w & 1;          // wv group: 0 -> wv 0-8, 1 -> wv 9-17
    const int row0 = ((w >> 1) << 5) + lane;   // 0..63
    const size_t rowBase = (size_t)blockIdx.x * TROWS;

    unsigned long long acc[2][9];
    #pragma unroll
    for (int i = 0; i < 2; i++)
        #pragma unroll
        for (int c = 0; c < 9; c++) acc[i][c] = 0ull;

    const float* xbase = x + rowBase * EE;

    #pragma unroll 1
    for (int ck = 0; ck < NCHUNK; ck++) {
        const int ce = ck * EK;

        // ---- stage x chunk: 128 rows x 60 floats (15 float4/row), swizzled
        #pragma unroll
        for (int it = 0; it < (TROWS * 15) / T1; it++) {
            int t = tid + it * T1;
            int row = t / 15, q = t % 15;
            float4 v = *reinterpret_cast<const float4*>(
                xbase + (size_t)row * EE + ce + q * 4);
            int rr = row & 15;
            float2* b2 = reinterpret_cast<float2*>(&xs[row * XSTR]);
            b2[(2 * q) ^ rr]     = make_float2(v.x, v.y);
            b2[(2 * q + 1) ^ rr] = make_float2(v.z, v.w);
        }

        // ---- stage w chunk: 18 rows x 60 floats (15 float4/row)
        #pragma unroll
        for (int it = 0; it < 3; it++) {      // 270 loads, 128 threads
            int t = tid + it * T1;
            if (t < NWV * 15) {
                int wr = t / 15, q = t % 15;
                const float* src;
                if (wr < 3)       src = aw3 + wr * EE;
                else if (wr < 8)  src = aw5 + (wr - 3) * EE;
                else if (wr < 15) src = aw7 + (wr - 8) * EE;
                else              src = (wr == 15) ? cw3 : (wr == 16) ? cw5 : cw7;
                *reinterpret_cast<float4*>(&ws[wr * WSTR + q * 4]) =
                    *reinterpret_cast<const float4*>(src + ce + q * 4);
            }
        }
        __syncthreads();

        // ---- compute
        #pragma unroll
        for (int e = 0; e < EK; e += 4) {
            unsigned long long wv0[9], wv1[9];
            #pragma unroll
            for (int c = 0; c < 9; c++) {
                ulonglong2 w2 = *reinterpret_cast<const ulonglong2*>(
                    &ws[(cgrp * 9 + c) * WSTR + e]);   // broadcast LDS.128
                wv0[c] = w2.x;
                wv1[c] = w2.y;
            }
            #pragma unroll
            for (int i = 0; i < 2; i++) {
                int row = row0 + 64 * i;
                const unsigned long long* xr =
                    reinterpret_cast<const unsigned long long*>(&xs[row * XSTR]);
                int rr = row & 15;
                unsigned long long xa = xr[(e / 2) ^ rr];
                unsigned long long xb = xr[(e / 2 + 1) ^ rr];
                #pragma unroll
                for (int c = 0; c < 9; c++) {
                    acc[i][c] = ffma2(xa, wv0[c], acc[i][c]);
                    acc[i][c] = ffma2(xb, wv1[c], acc[i][c]);
                }
            }
        }
        __syncthreads();
    }

    // ---- reduce f32x2 pairs, stage into smem (reuse xs), write coalesced
    #pragma unroll
    for (int i = 0; i < 2; i++) {
        int row = row0 + 64 * i;
        #pragma unroll
        for (int c = 0; c < 9; c++) {
            float lo, hi;
            asm("mov.b64 {%0,%1}, %2;" : "=f"(lo), "=f"(hi) : "l"(acc[i][c]));
            xs[row * NWV + cgrp * 9 + c] = lo + hi;
        }
    }
    __syncthreads();

    float* qdst = g_Q + rowBase * NWV;   // block's 128*18 region is contiguous
    #pragma unroll
    for (int t = tid; t < TROWS * NWV / 4; t += T1) {
        *reinterpret_cast<float4*>(qdst + t * 4) =
            *reinterpret_cast<const float4*>(&xs[t * 4]);
    }
}

// ---------------------------------------------------------------------------
// Kernel 2: shift-combine + activations (per-thread, R5 version — measured
// faster than the smem-tiled variant)
// ---------------------------------------------------------------------------
__global__ void combine_kernel(
    const float* __restrict__ ab3, const float* __restrict__ cb3,
    const float* __restrict__ ab5, const float* __restrict__ cb5,
    const float* __restrict__ ab7, const float* __restrict__ cb7,
    float* __restrict__ out)
{
    int row = blockIdx.x * blockDim.x + threadIdx.x;
    if (row >= NROWS) return;
    int l = row % LL;
    const float* q = g_Q + (size_t)row * NWV;

    float s3 = 0.f, s5 = 0.f, s7 = 0.f;
    #pragma unroll
    for (int j = 0; j < 3; j++) {
        int d = j - 1, nl = l + d;
        if (nl >= 0 && nl < LL) s3 += q[(long)d * NWV + j];
    }
    #pragma unroll
    for (int j = 0; j < 5; j++) {
        int d = j - 2, nl = l + d;
        if (nl >= 0 && nl < LL) s5 += q[(long)d * NWV + 3 + j];
    }
    #pragma unroll
    for (int j = 0; j < 7; j++) {
        int d = j - 3, nl = l + d;
        if (nl >= 0 && nl < LL) s7 += q[(long)d * NWV + 8 + j];
    }

    float d3 = q[15], d5 = q[16], d7 = q[17];
    float sc3 = 1.f / (1.f + __expf(-(s3 + ab3[0])));
    float sc5 = 1.f / (1.f + __expf(-(s5 + ab5[0])));
    float sc7 = 1.f / (1.f + __expf(-(s7 + ab7[0])));

    out[row]             = tanhf(sc3 * d3 + cb3[0]);
    out[NROWS + row]     = tanhf(sc5 * d5 + cb5[0]);
    out[2 * NROWS + row] = tanhf(sc7 * d7 + cb7[0]);
}

// ---------------------------------------------------------------------------
extern "C" void kernel_launch(void* const* d_in, const int* in_sizes, int n_in,
                              void* d_out, int out_size) {
    const float* x   = (const float*)d_in[0];
    const float* aw3 = (const float*)d_in[1];
    const float* ab3 = (const float*)d_in[2];
    const float* cw3 = (const float*)d_in[3];
    const float* cb3 = (const float*)d_in[4];
    const float* aw5 = (const float*)d_in[5];
    const float* ab5 = (const float*)d_in[6];
    const float* cw5 = (const float*)d_in[7];
    const float* cb5 = (const float*)d_in[8];
    const float* aw7 = (const float*)d_in[9];
    const float* ab7 = (const float*)d_in[10];
    const float* cw7 = (const float*)d_in[11];
    const float* cb7 = (const float*)d_in[12];
    float* out = (float*)d_out;

    dots_kernel<<<NROWS / TROWS, T1>>>(x, aw3, aw5, aw7, cw3, cw5, cw7);
    combine_kernel<<<(NROWS + 255) / 256, 256>>>(ab3, cb3, ab5, cb5, ab7, cb7, out);
}